// round 16
// baseline (speedup 1.0000x reference)
#include <cuda_runtime.h>
#include <cuda_fp16.h>
#include <math.h>
#include <stdint.h>

// SupervisedContrastiveLoss — symmetric fp16 mma.sync Gram (f16 accumulators)
// + f16x2 ex2 + bilinear positive-sum trick. Plain-sm_100-safe.
// R16 (= R15 resubmit; infra failure last round): f16 acc frees 32 regs ->
//      2-deep LDSM/HMMA software pipeline in the mainloop. Epilogue consumes
//      f16x2 acc directly. Structure otherwise = R14 (3-stage, proven).

#define BSZ 8192
#define DIM 256
#define NTC 64                       // 64x64 grid of 128x128 tiles
#define NTRI (NTC * (NTC + 1) / 2)   // 2080 upper-tri tiles
#define NCTAS 296                    // 2 CTAs per SM
#define NLAB 128

// K-chunked smem: chunk = 64 fp16 = 128B per row, pad to 144B
#define ROWB 144
#define APANEL (128 * ROWB)          // 18432
#define STAGEB (2 * APANEL)          // 36864 (A panel + B panel)
#define NSTG 3
#define SMEM_TOTAL (NSTG * STAGEB)   // 110592 (3 stages; 2 CTAs = 221KB)

#define KEXPF 14.4269504088896f      // 10 * log2(e)

__device__ __half g_f16[BSZ * DIM];
__device__ float g_denom[BSZ];
__device__ float g_S[NLAB * DIM];
__device__ int   g_cnt[NLAB];
__device__ int   g_lab[BSZ];
__device__ float g_fsum;
__device__ float g_fcnt;
__device__ unsigned g_ticket;

// ---------------- helpers ----------------
__device__ __forceinline__ uint32_t smem_u32(const void* p) {
    uint32_t a;
    asm("{ .reg .u64 t; cvta.to.shared.u64 t, %1; cvt.u32.u64 %0, t; }"
        : "=r"(a) : "l"(p));
    return a;
}
__device__ __forceinline__ void cp16(uint32_t dst, const void* src) {
    asm volatile("cp.async.cg.shared.global [%0], [%1], 16;"
                 :: "r"(dst), "l"((uint64_t)__cvta_generic_to_global(src))
                 : "memory");
}
__device__ __forceinline__ void ldmx4(uint32_t a, uint32_t& r0, uint32_t& r1,
                                      uint32_t& r2, uint32_t& r3) {
    asm volatile("ldmatrix.sync.aligned.m8n8.x4.shared.b16 {%0,%1,%2,%3}, [%4];"
                 : "=r"(r0), "=r"(r1), "=r"(r2), "=r"(r3) : "r"(a));
}
// f16-accumulator MMA: D,C = 2x b32 (f16x2), A = 4x b32, B = 2x b32
__device__ __forceinline__ void mma_f16acc(uint32_t* c, const uint32_t* a,
                                           const uint32_t* b) {
    asm volatile(
        "mma.sync.aligned.m16n8k16.row.col.f16.f16.f16.f16 "
        "{%0,%1}, {%2,%3,%4,%5}, {%6,%7}, {%0,%1};"
        : "+r"(c[0]), "+r"(c[1])
        : "r"(a[0]), "r"(a[1]), "r"(a[2]), "r"(a[3]), "r"(b[0]), "r"(b[1]));
}
__device__ __forceinline__ __half2 shfl_xor_h2(__half2 v, int m) {
    uint32_t u = *reinterpret_cast<uint32_t*>(&v);
    u = __shfl_xor_sync(0xffffffffu, u, m);
    return *reinterpret_cast<__half2*>(&u);
}

// ---------------- prep0: parallel zeroing (grid 64) ------------------------
__global__ void prep0_kernel() {
    int i = blockIdx.x * 256 + threadIdx.x;   // 16384 threads
    g_S[i] = 0.f;
    g_S[i + 16384] = 0.f;
    if (i < BSZ) g_denom[i] = 0.f;
    if (i < NLAB) g_cnt[i] = 0;
    if (i == 0) { g_fsum = 0.f; g_fcnt = 0.f; g_ticket = 0u; }
}

// ---------------- prep1: label detect/convert + hist (grid 32) -------------
__global__ void prep1_kernel(const int* __restrict__ labraw) {
    __shared__ int h[NLAB];
    int t = threadIdx.x;
    for (int i = t; i < NLAB; i += 256) h[i] = 0;
    int nz = 0;
    for (int i = t; i < BSZ / 2; i += 256)
        nz |= (labraw[2 * i + 1] != 0);
    int is64 = !__syncthreads_or(nz);
    int i = blockIdx.x * 256 + t;
    int lab = (is64 ? labraw[2 * i] : labraw[i]) & (NLAB - 1);
    g_lab[i] = lab;
    atomicAdd(&h[lab], 1);
    __syncthreads();
    for (int k = t; k < NLAB; k += 256)
        if (h[k]) atomicAdd(&g_cnt[k], h[k]);
}

// ---------------- normalize + fused label-sum (REDG); fp16 store -----------
__global__ void normalize_kernel(const float* __restrict__ lat) {
    int r = blockIdx.x, t = threadIdx.x;
    float v = lat[r * DIM + t];
    float ss = v * v;
    #pragma unroll
    for (int o = 16; o > 0; o >>= 1)
        ss += __shfl_xor_sync(0xffffffffu, ss, o);
    __shared__ float ws[8];
    int w = t >> 5, l = t & 31;
    if (l == 0) ws[w] = ss;
    __syncthreads();
    if (w == 0) {
        float s = (l < 8) ? ws[l] : 0.f;
        #pragma unroll
        for (int o = 4; o > 0; o >>= 1)
            s += __shfl_xor_sync(0xffffffffu, s, o);
        if (l == 0) ws[0] = s;
    }
    __syncthreads();
    float n = v * (1.f / fmaxf(sqrtf(ws[0]), 1e-8f));
    g_f16[r * DIM + t] = __float2half(n);
    atomicAdd(&g_S[g_lab[r] * DIM + t], n);
}

// ---------------- main kernel: tri tiles, 3-stage distance-2 pipeline ------
__global__ void __launch_bounds__(256, 2) simdenom_kernel() {
    extern __shared__ __align__(128) char smem[];
    __shared__ int sc_r, sc_o;       // current-tile coords for the epilogue
    const uint32_t sbase = smem_u32(smem);
    const int tid = threadIdx.x;
    const int wid = tid >> 5;
    const int lane = tid & 31;
    const int wm = wid & 3;
    const int wn = wid >> 2;
    const int tq = lane >> 2;
    const int tr = lane & 3;

    const int arow = (lane & 7) + ((lane >> 3) & 1) * 8;
    const int akof = (lane >> 4) * 8;
    const int brow = (lane & 7) + (lane >> 4) * 8;
    const int bkof = ((lane >> 3) & 1) * 8;

    int ntl = (NTRI - (int)blockIdx.x + NCTAS - 1) / NCTAS;
    const int nseq = ntl * 4;    // 4 K-chunks of 64 per tile

    int rr = 0, oo = blockIdx.x;
    while (oo >= NTC - rr) { oo -= (NTC - rr); rr++; }
    auto step = [&](int& r_, int& o_) {
        o_ += NCTAS;
        while (o_ >= NTC - r_) { o_ -= (NTC - r_); r_++; }
    };

    auto issue = [&](int r_, int o_, int c) {
        const int r0 = r_ * 128, c0 = (r_ + o_) * 128;
        const int koff = (c & 3) * 64;
        const uint32_t stg = sbase + (uint32_t)(c % NSTG) * STAGEB;
        #pragma unroll
        for (int u = 0; u < 8; u++) {
            int g = tid + u * 256;          // 0..2047
            int panel = g >> 10;            // 0=A, 1=B
            int idx = g & 1023;
            int row = idx >> 3, ci = idx & 7;
            int base = panel ? c0 : r0;
            const void* src = &g_f16[(size_t)(base + row) * DIM + koff + ci * 8];
            cp16(stg + (uint32_t)panel * APANEL + row * ROWB + ci * 16, src);
        }
        asm volatile("cp.async.commit_group;" ::: "memory");
    };

    uint32_t acc[2][8][2];               // f16x2 accumulators (32 regs)
    const __half2 K2 = __half2half2(__float2half(KEXPF));

    // prologue: chunks 0 and 1 (both in this CTA's first tile)
    if (tid == 0) { sc_r = rr; sc_o = oo; }
    issue(rr, oo, 0);
    issue(rr, oo, 1);

    #pragma unroll 1
    for (int s = 0; s < nseq; s++) {
        const int chunk = s & 3;

        if (chunk == 2) {
            if (tid == 0) { sc_r = rr; sc_o = oo; }
            if (s + 2 < nseq) {
                step(rr, oo);
                issue(rr, oo, s + 2);
                asm volatile("cp.async.wait_group 2;" ::: "memory");
            } else if (s + 1 < nseq) {
                asm volatile("cp.async.wait_group 1;" ::: "memory");
            } else {
                asm volatile("cp.async.wait_group 0;" ::: "memory");
            }
        } else {
            if (s + 2 < nseq) {
                issue(rr, oo, s + 2);
                asm volatile("cp.async.wait_group 2;" ::: "memory");
            } else if (s + 1 < nseq) {
                asm volatile("cp.async.wait_group 1;" ::: "memory");
            } else {
                asm volatile("cp.async.wait_group 0;" ::: "memory");
            }
        }
        __syncthreads();

        if (chunk == 0) {
            #pragma unroll
            for (int mt = 0; mt < 2; mt++)
                #pragma unroll
                for (int nt = 0; nt < 8; nt++) {
                    acc[mt][nt][0] = 0u;
                    acc[mt][nt][1] = 0u;
                }
        }

        // ---- GEMM on stage s%3: 4 k-steps, 2-deep fragment pipeline ----
        const uint32_t sA = sbase + (uint32_t)(s % NSTG) * STAGEB;
        const uint32_t sB = sA + APANEL;
        uint32_t aBase0 = sA + (wm * 32 + 0  + arow) * ROWB + akof * 2;
        uint32_t aBase1 = sA + (wm * 32 + 16 + arow) * ROWB + akof * 2;
        uint32_t bBase[4];
        #pragma unroll
        for (int p = 0; p < 4; p++)
            bBase[p] = sB + (wn * 64 + p * 16 + brow) * ROWB + bkof * 2;

        uint32_t afr[2][2][4], bfr[2][8][2];
        // preload k-step 0 into buffer 0
        ldmx4(aBase0, afr[0][0][0], afr[0][0][1], afr[0][0][2], afr[0][0][3]);
        ldmx4(aBase1, afr[0][1][0], afr[0][1][1], afr[0][1][2], afr[0][1][3]);
        #pragma unroll
        for (int p = 0; p < 4; p++)
            ldmx4(bBase[p], bfr[0][2*p][0], bfr[0][2*p][1],
                  bfr[0][2*p+1][0], bfr[0][2*p+1][1]);

        #pragma unroll
        for (int ks = 0; ks < 4; ks++) {
            const int cur = ks & 1, nxt = cur ^ 1;
            if (ks < 3) {
                ldmx4(aBase0 + (ks+1) * 32, afr[nxt][0][0], afr[nxt][0][1],
                      afr[nxt][0][2], afr[nxt][0][3]);
                ldmx4(aBase1 + (ks+1) * 32, afr[nxt][1][0], afr[nxt][1][1],
                      afr[nxt][1][2], afr[nxt][1][3]);
                #pragma unroll
                for (int p = 0; p < 4; p++)
                    ldmx4(bBase[p] + (ks+1) * 32,
                          bfr[nxt][2*p][0], bfr[nxt][2*p][1],
                          bfr[nxt][2*p+1][0], bfr[nxt][2*p+1][1]);
            }
            #pragma unroll
            for (int mt = 0; mt < 2; mt++)
                #pragma unroll
                for (int nt = 0; nt < 8; nt++)
                    mma_f16acc(acc[mt][nt], afr[cur][mt], bfr[cur][nt]);
        }

        // ---- epilogue after the 4th chunk; coords come from smem ----
        if (chunk == 3) {
            const int er = sc_r, eo = sc_o;
            const int r0 = er * 128, c0 = (er + eo) * 128;
            const bool diag = (eo == 0);
            if (!diag) {
                __half2 rh[4], ch[8];
                #pragma unroll
                for (int i = 0; i < 4; i++) rh[i] = __half2half2(__ushort_as_half(0));
                #pragma unroll
                for (int i = 0; i < 8; i++) ch[i] = __half2half2(__ushort_as_half(0));
                #pragma unroll
                for (int mt = 0; mt < 2; mt++) {
                    #pragma unroll
                    for (int nt = 0; nt < 8; nt++) {
                        __half2 c0h = *reinterpret_cast<__half2*>(&acc[mt][nt][0]);
                        __half2 c1h = *reinterpret_cast<__half2*>(&acc[mt][nt][1]);
                        __half2 e0 = h2exp2(__hmul2(c0h, K2));  // row tq
                        __half2 e1 = h2exp2(__hmul2(c1h, K2));  // row tq+8
                        rh[mt*2+0] = __hadd2(rh[mt*2+0], e0);
                        rh[mt*2+1] = __hadd2(rh[mt*2+1], e1);
                        ch[nt] = __hadd2(ch[nt], __hadd2(e0, e1));
                    }
                }
                float rs[4];
                #pragma unroll
                for (int i = 0; i < 4; i++)
                    rs[i] = __low2float(rh[i]) + __high2float(rh[i]);
                #pragma unroll
                for (int o = 1; o <= 2; o <<= 1)
                    #pragma unroll
                    for (int i = 0; i < 4; i++)
                        rs[i] += __shfl_xor_sync(0xffffffffu, rs[i], o);
                if (tr == 0) {
                    #pragma unroll
                    for (int i = 0; i < 4; i++) {
                        int gr = r0 + wm * 32 + (i >> 1) * 16 + tq + (i & 1) * 8;
                        atomicAdd(&g_denom[gr], rs[i]);
                    }
                }
                #pragma unroll
                for (int o = 4; o <= 16; o <<= 1)
                    #pragma unroll
                    for (int i = 0; i < 8; i++)
                        ch[i] = __hadd2(ch[i], shfl_xor_h2(ch[i], o));
                if (tq == 0) {
                    #pragma unroll
                    for (int i = 0; i < 8; i++) {
                        int gc = c0 + wn * 64 + i * 8 + tr * 2;
                        atomicAdd(&g_denom[gc],     __low2float(ch[i]));
                        atomicAdd(&g_denom[gc + 1], __high2float(ch[i]));
                    }
                }
            } else {
                float rs[4] = {0.f, 0.f, 0.f, 0.f};
                #pragma unroll
                for (int mt = 0; mt < 2; mt++) {
                    #pragma unroll
                    for (int nt = 0; nt < 8; nt++) {
                        float2 f0 = __half22float2(
                            *reinterpret_cast<__half2*>(&acc[mt][nt][0]));
                        float2 f1 = __half22float2(
                            *reinterpret_cast<__half2*>(&acc[mt][nt][1]));
                        int rin0 = wm * 32 + mt * 16 + tq;
                        int rin1 = rin0 + 8;
                        int cin0 = wn * 64 + nt * 8 + tr * 2;
                        if (rin0 != cin0)     rs[mt*2+0] += __expf(10.f * f0.x);
                        if (rin0 != cin0 + 1) rs[mt*2+0] += __expf(10.f * f0.y);
                        if (rin1 != cin0)     rs[mt*2+1] += __expf(10.f * f1.x);
                        if (rin1 != cin0 + 1) rs[mt*2+1] += __expf(10.f * f1.y);
                    }
                }
                #pragma unroll
                for (int o = 1; o <= 2; o <<= 1)
                    #pragma unroll
                    for (int i = 0; i < 4; i++)
                        rs[i] += __shfl_xor_sync(0xffffffffu, rs[i], o);
                if (tr == 0) {
                    #pragma unroll
                    for (int i = 0; i < 4; i++) {
                        int gr = r0 + wm * 32 + (i >> 1) * 16 + tq + (i & 1) * 8;
                        atomicAdd(&g_denom[gr], rs[i]);
                    }
                }
            }
        }
        __syncthreads();
    }
}

// ---------------- finalize: possum (fp16 path) + loss + last-block write ---
__global__ void finalize1_kernel(float* __restrict__ out) {
    int t = threadIdx.x, w = t >> 5, l = t & 31;
    int r = blockIdx.x * 8 + w;
    int lab = g_lab[r];
    const __half2* np = (const __half2*)&g_f16[r * DIM + l * 8];
    const float4* sp = (const float4*)&g_S[lab * DIM + l * 8];
    float2 n0 = __half22float2(np[0]);
    float2 n1 = __half22float2(np[1]);
    float2 n2 = __half22float2(np[2]);
    float2 n3 = __half22float2(np[3]);
    float4 s0 = sp[0], s1 = sp[1];
    float ps = n0.x*s0.x + n0.y*s0.y + n1.x*s0.z + n1.y*s0.w +
               n2.x*s1.x + n2.y*s1.y + n3.x*s1.z + n3.y*s1.w;
    float sd = n0.x*n0.x + n0.y*n0.y + n1.x*n1.x + n1.y*n1.y +
               n2.x*n2.x + n2.y*n2.y + n3.x*n3.x + n3.y*n3.y;
    #pragma unroll
    for (int o = 16; o > 0; o >>= 1) {
        ps += __shfl_xor_sync(0xffffffffu, ps, o);
        sd += __shfl_xor_sync(0xffffffffu, sd, o);
    }
    __shared__ float bs[8], bn[8];
    __shared__ bool amLast;
    if (l == 0) {
        float np_cnt = (float)(g_cnt[lab] - 1);
        float s = 0.f, n = 0.f;
        if (np_cnt > 0.5f) {
            float possum = 10.f * (ps - sd);
            s = logf(fmaxf(g_denom[r], 1e-8f)) - possum / np_cnt;
            n = 1.f;
        }
        bs[w] = s; bn[w] = n;
    }
    __syncthreads();
    if (t == 0) {
        float S = 0.f, N = 0.f;
        #pragma unroll
        for (int k = 0; k < 8; k++) { S += bs[k]; N += bn[k]; }
        atomicAdd(&g_fsum, S);
        atomicAdd(&g_fcnt, N);
        __threadfence();
        unsigned v = atomicInc(&g_ticket, (unsigned)(BSZ / 8) - 1u);
        amLast = (v == (unsigned)(BSZ / 8) - 1u);
    }
    __syncthreads();
    if (amLast && t == 0) {
        float S = *(volatile float*)&g_fsum;
        float N = *(volatile float*)&g_fcnt;
        out[0] = S / fmaxf(N, 1.f);
    }
}

// ---------------------------------------------------------------------------
extern "C" void kernel_launch(void* const* d_in, const int* in_sizes, int n_in,
                              void* d_out, int out_size) {
    const float* lat    = (const float*)d_in[0];
    const int*   labraw = (const int*)d_in[1];
    float*       out    = (float*)d_out;

    cudaFuncSetAttribute(simdenom_kernel,
                         cudaFuncAttributeMaxDynamicSharedMemorySize,
                         SMEM_TOTAL);

    prep0_kernel<<<64, 256>>>();
    prep1_kernel<<<32, 256>>>(labraw);
    normalize_kernel<<<BSZ, DIM>>>(lat);
    simdenom_kernel<<<NCTAS, 256, SMEM_TOTAL>>>();
    finalize1_kernel<<<BSZ / 8, 256>>>(out);

    (void)in_sizes; (void)n_in; (void)out_size;
}

// round 17
// speedup vs baseline: 1.0511x; 1.0511x over previous
#include <cuda_runtime.h>
#include <cuda_fp16.h>
#include <math.h>
#include <stdint.h>

// SupervisedContrastiveLoss — symmetric fp16 mma.sync Gram (f16 accumulators)
// + f16x2 ex2 + bilinear positive-sum trick. Plain-sm_100-safe.
// R17: 3 CTAs/SM. R8's proven 2-stage distance-1 skeleton + f16 acc
//      (32 regs) + single-buffered fragments, __launch_bounds__(256,3),
//      2-stage smem (73.7KB/CTA -> 3 CTAs = 221KB/SM). 444 CTAs.

#define BSZ 8192
#define DIM 256
#define NTC 64                       // 64x64 grid of 128x128 tiles
#define NTRI (NTC * (NTC + 1) / 2)   // 2080 upper-tri tiles
#define NCTAS 444                    // 3 CTAs per SM
#define NLAB 128

// K-chunked smem: chunk = 64 fp16 = 128B per row, pad to 144B
#define ROWB 144
#define APANEL (128 * ROWB)          // 18432
#define STAGEB (2 * APANEL)          // 36864 (A panel + B panel)
#define SMEM_TOTAL (2 * STAGEB)      // 73728 (2 pipeline stages)

#define KEXPF 14.4269504088896f      // 10 * log2(e)

__device__ __half g_f16[BSZ * DIM];
__device__ float g_denom[BSZ];
__device__ float g_S[NLAB * DIM];
__device__ int   g_cnt[NLAB];
__device__ int   g_lab[BSZ];
__device__ float g_fsum;
__device__ float g_fcnt;
__device__ unsigned g_ticket;

// ---------------- helpers ----------------
__device__ __forceinline__ uint32_t smem_u32(const void* p) {
    uint32_t a;
    asm("{ .reg .u64 t; cvta.to.shared.u64 t, %1; cvt.u32.u64 %0, t; }"
        : "=r"(a) : "l"(p));
    return a;
}
__device__ __forceinline__ void cp16(uint32_t dst, const void* src) {
    asm volatile("cp.async.cg.shared.global [%0], [%1], 16;"
                 :: "r"(dst), "l"((uint64_t)__cvta_generic_to_global(src))
                 : "memory");
}
__device__ __forceinline__ void ldmx4(uint32_t a, uint32_t& r0, uint32_t& r1,
                                      uint32_t& r2, uint32_t& r3) {
    asm volatile("ldmatrix.sync.aligned.m8n8.x4.shared.b16 {%0,%1,%2,%3}, [%4];"
                 : "=r"(r0), "=r"(r1), "=r"(r2), "=r"(r3) : "r"(a));
}
// f16-accumulator MMA: D,C = 2x b32 (f16x2), A = 4x b32, B = 2x b32
__device__ __forceinline__ void mma_f16acc(uint32_t* c, const uint32_t* a,
                                           const uint32_t* b) {
    asm volatile(
        "mma.sync.aligned.m16n8k16.row.col.f16.f16.f16.f16 "
        "{%0,%1}, {%2,%3,%4,%5}, {%6,%7}, {%0,%1};"
        : "+r"(c[0]), "+r"(c[1])
        : "r"(a[0]), "r"(a[1]), "r"(a[2]), "r"(a[3]), "r"(b[0]), "r"(b[1]));
}
__device__ __forceinline__ __half2 shfl_xor_h2(__half2 v, int m) {
    uint32_t u = *reinterpret_cast<uint32_t*>(&v);
    u = __shfl_xor_sync(0xffffffffu, u, m);
    return *reinterpret_cast<__half2*>(&u);
}

// ---------------- prep0: parallel zeroing (grid 64) ------------------------
__global__ void prep0_kernel() {
    int i = blockIdx.x * 256 + threadIdx.x;   // 16384 threads
    g_S[i] = 0.f;
    g_S[i + 16384] = 0.f;
    if (i < BSZ) g_denom[i] = 0.f;
    if (i < NLAB) g_cnt[i] = 0;
    if (i == 0) { g_fsum = 0.f; g_fcnt = 0.f; g_ticket = 0u; }
}

// ---------------- prep1: label detect/convert + hist (grid 32) -------------
__global__ void prep1_kernel(const int* __restrict__ labraw) {
    __shared__ int h[NLAB];
    int t = threadIdx.x;
    for (int i = t; i < NLAB; i += 256) h[i] = 0;
    int nz = 0;
    for (int i = t; i < BSZ / 2; i += 256)
        nz |= (labraw[2 * i + 1] != 0);
    int is64 = !__syncthreads_or(nz);
    int i = blockIdx.x * 256 + t;
    int lab = (is64 ? labraw[2 * i] : labraw[i]) & (NLAB - 1);
    g_lab[i] = lab;
    atomicAdd(&h[lab], 1);
    __syncthreads();
    for (int k = t; k < NLAB; k += 256)
        if (h[k]) atomicAdd(&g_cnt[k], h[k]);
}

// ---------------- normalize + fused label-sum (REDG); fp16 store -----------
__global__ void normalize_kernel(const float* __restrict__ lat) {
    int r = blockIdx.x, t = threadIdx.x;
    float v = lat[r * DIM + t];
    float ss = v * v;
    #pragma unroll
    for (int o = 16; o > 0; o >>= 1)
        ss += __shfl_xor_sync(0xffffffffu, ss, o);
    __shared__ float ws[8];
    int w = t >> 5, l = t & 31;
    if (l == 0) ws[w] = ss;
    __syncthreads();
    if (w == 0) {
        float s = (l < 8) ? ws[l] : 0.f;
        #pragma unroll
        for (int o = 4; o > 0; o >>= 1)
            s += __shfl_xor_sync(0xffffffffu, s, o);
        if (l == 0) ws[0] = s;
    }
    __syncthreads();
    float n = v * (1.f / fmaxf(sqrtf(ws[0]), 1e-8f));
    g_f16[r * DIM + t] = __float2half(n);
    atomicAdd(&g_S[g_lab[r] * DIM + t], n);
}

// ---------------- main kernel: tri tiles, 2-stage pipeline, 3 CTAs/SM ------
__global__ void __launch_bounds__(256, 3) simdenom_kernel() {
    extern __shared__ __align__(128) char smem[];
    const uint32_t sbase = smem_u32(smem);
    const int tid = threadIdx.x;
    const int wid = tid >> 5;
    const int lane = tid & 31;
    const int wm = wid & 3;
    const int wn = wid >> 2;
    const int tq = lane >> 2;
    const int tr = lane & 3;

    const int arow = (lane & 7) + ((lane >> 3) & 1) * 8;
    const int akof = (lane >> 4) * 8;
    const int brow = (lane & 7) + (lane >> 4) * 8;
    const int bkof = ((lane >> 3) & 1) * 8;

    int ntl = (NTRI - (int)blockIdx.x + NCTAS - 1) / NCTAS;
    const int nseq = ntl * 4;    // 4 K-chunks of 64 per tile

    // cursor: tile q -> (rr, oo), oo = cc - rr
    int rr = 0, oo = blockIdx.x;
    while (oo >= NTC - rr) { oo -= (NTC - rr); rr++; }
    auto step = [&](int& r_, int& o_) {
        o_ += NCTAS;
        while (o_ >= NTC - r_) { o_ -= (NTC - r_); r_++; }
    };

    // issue chunk loads for tile (r_, o_), sequence slot s (stage s&1)
    auto issue = [&](int r_, int o_, int s) {
        const int r0 = r_ * 128, c0 = (r_ + o_) * 128;
        const int koff = (s & 3) * 64;
        const uint32_t stg = sbase + (uint32_t)(s & 1) * STAGEB;
        #pragma unroll
        for (int u = 0; u < 8; u++) {
            int g = tid + u * 256;          // 0..2047
            int panel = g >> 10;            // 0=A, 1=B
            int idx = g & 1023;
            int row = idx >> 3, ci = idx & 7;
            int base = panel ? c0 : r0;
            const void* src = &g_f16[(size_t)(base + row) * DIM + koff + ci * 8];
            cp16(stg + (uint32_t)panel * APANEL + row * ROWB + ci * 16, src);
        }
        asm volatile("cp.async.commit_group;" ::: "memory");
    };

    uint32_t acc[2][8][2];               // f16x2 accumulators (32 regs)
    const __half2 K2 = __half2half2(__float2half(KEXPF));

    if (nseq > 0) issue(rr, oo, 0);

    #pragma unroll 1
    for (int s = 0; s < nseq; s++) {
        const int chunk = s & 3;
        int nrr = rr, noo = oo;
        if (s + 1 < nseq) {
            if (chunk == 3) {
                step(nrr, noo);
                issue(nrr, noo, s + 1);
            } else {
                issue(rr, oo, s + 1);
            }
            asm volatile("cp.async.wait_group 1;" ::: "memory");
        } else {
            asm volatile("cp.async.wait_group 0;" ::: "memory");
        }
        __syncthreads();

        if (chunk == 0) {
            #pragma unroll
            for (int mt = 0; mt < 2; mt++)
                #pragma unroll
                for (int nt = 0; nt < 8; nt++) {
                    acc[mt][nt][0] = 0u;
                    acc[mt][nt][1] = 0u;
                }
        }

        // ---- GEMM on current stage: 4 k-steps of 16 (single-buffer) ----
        const uint32_t sA = sbase + (uint32_t)(s & 1) * STAGEB;
        const uint32_t sB = sA + APANEL;
        uint32_t aBase0 = sA + (wm * 32 + 0  + arow) * ROWB + akof * 2;
        uint32_t aBase1 = sA + (wm * 32 + 16 + arow) * ROWB + akof * 2;
        uint32_t bBase[4];
        #pragma unroll
        for (int p = 0; p < 4; p++)
            bBase[p] = sB + (wn * 64 + p * 16 + brow) * ROWB + bkof * 2;

        #pragma unroll
        for (int ks = 0; ks < 4; ks++) {
            uint32_t a[2][4], b[8][2];
            ldmx4(aBase0 + ks * 32, a[0][0], a[0][1], a[0][2], a[0][3]);
            ldmx4(aBase1 + ks * 32, a[1][0], a[1][1], a[1][2], a[1][3]);
            #pragma unroll
            for (int p = 0; p < 4; p++)
                ldmx4(bBase[p] + ks * 32, b[2*p][0], b[2*p][1],
                      b[2*p+1][0], b[2*p+1][1]);
            #pragma unroll
            for (int mt = 0; mt < 2; mt++)
                #pragma unroll
                for (int nt = 0; nt < 8; nt++)
                    mma_f16acc(acc[mt][nt], a[mt], b[nt]);
        }

        // ---- epilogue after the 4th chunk ----
        if (chunk == 3) {
            const int r0 = rr * 128, c0 = (rr + oo) * 128;
            const bool diag = (oo == 0);
            if (!diag) {
                __half2 rh[4], ch[8];
                #pragma unroll
                for (int i = 0; i < 4; i++) rh[i] = __half2half2(__ushort_as_half(0));
                #pragma unroll
                for (int i = 0; i < 8; i++) ch[i] = __half2half2(__ushort_as_half(0));
                #pragma unroll
                for (int mt = 0; mt < 2; mt++) {
                    #pragma unroll
                    for (int nt = 0; nt < 8; nt++) {
                        __half2 c0h = *reinterpret_cast<__half2*>(&acc[mt][nt][0]);
                        __half2 c1h = *reinterpret_cast<__half2*>(&acc[mt][nt][1]);
                        __half2 e0 = h2exp2(__hmul2(c0h, K2));  // row tq
                        __half2 e1 = h2exp2(__hmul2(c1h, K2));  // row tq+8
                        rh[mt*2+0] = __hadd2(rh[mt*2+0], e0);
                        rh[mt*2+1] = __hadd2(rh[mt*2+1], e1);
                        ch[nt] = __hadd2(ch[nt], __hadd2(e0, e1));
                    }
                }
                float rs[4];
                #pragma unroll
                for (int i = 0; i < 4; i++)
                    rs[i] = __low2float(rh[i]) + __high2float(rh[i]);
                #pragma unroll
                for (int o = 1; o <= 2; o <<= 1)
                    #pragma unroll
                    for (int i = 0; i < 4; i++)
                        rs[i] += __shfl_xor_sync(0xffffffffu, rs[i], o);
                if (tr == 0) {
                    #pragma unroll
                    for (int i = 0; i < 4; i++) {
                        int gr = r0 + wm * 32 + (i >> 1) * 16 + tq + (i & 1) * 8;
                        atomicAdd(&g_denom[gr], rs[i]);
                    }
                }
                #pragma unroll
                for (int o = 4; o <= 16; o <<= 1)
                    #pragma unroll
                    for (int i = 0; i < 8; i++)
                        ch[i] = __hadd2(ch[i], shfl_xor_h2(ch[i], o));
                if (tq == 0) {
                    #pragma unroll
                    for (int i = 0; i < 8; i++) {
                        int gc = c0 + wn * 64 + i * 8 + tr * 2;
                        atomicAdd(&g_denom[gc],     __low2float(ch[i]));
                        atomicAdd(&g_denom[gc + 1], __high2float(ch[i]));
                    }
                }
            } else {
                float rs[4] = {0.f, 0.f, 0.f, 0.f};
                #pragma unroll
                for (int mt = 0; mt < 2; mt++) {
                    #pragma unroll
                    for (int nt = 0; nt < 8; nt++) {
                        float2 f0 = __half22float2(
                            *reinterpret_cast<__half2*>(&acc[mt][nt][0]));
                        float2 f1 = __half22float2(
                            *reinterpret_cast<__half2*>(&acc[mt][nt][1]));
                        int rin0 = wm * 32 + mt * 16 + tq;
                        int rin1 = rin0 + 8;
                        int cin0 = wn * 64 + nt * 8 + tr * 2;
                        if (rin0 != cin0)     rs[mt*2+0] += __expf(10.f * f0.x);
                        if (rin0 != cin0 + 1) rs[mt*2+0] += __expf(10.f * f0.y);
                        if (rin1 != cin0)     rs[mt*2+1] += __expf(10.f * f1.x);
                        if (rin1 != cin0 + 1) rs[mt*2+1] += __expf(10.f * f1.y);
                    }
                }
                #pragma unroll
                for (int o = 1; o <= 2; o <<= 1)
                    #pragma unroll
                    for (int i = 0; i < 4; i++)
                        rs[i] += __shfl_xor_sync(0xffffffffu, rs[i], o);
                if (tr == 0) {
                    #pragma unroll
                    for (int i = 0; i < 4; i++) {
                        int gr = r0 + wm * 32 + (i >> 1) * 16 + tq + (i & 1) * 8;
                        atomicAdd(&g_denom[gr], rs[i]);
                    }
                }
            }
            rr = nrr; oo = noo;
        }
        __syncthreads();
    }
}

// ---------------- finalize: possum (fp16 path) + loss + last-block write ---
__global__ void finalize1_kernel(float* __restrict__ out) {
    int t = threadIdx.x, w = t >> 5, l = t & 31;
    int r = blockIdx.x * 8 + w;
    int lab = g_lab[r];
    const __half2* np = (const __half2*)&g_f16[r * DIM + l * 8];
    const float4* sp = (const float4*)&g_S[lab * DIM + l * 8];
    float2 n0 = __half22float2(np[0]);
    float2 n1 = __half22float2(np[1]);
    float2 n2 = __half22float2(np[2]);
    float2 n3 = __half22float2(np[3]);
    float4 s0 = sp[0], s1 = sp[1];
    float ps = n0.x*s0.x + n0.y*s0.y + n1.x*s0.z + n1.y*s0.w +
               n2.x*s1.x + n2.y*s1.y + n3.x*s1.z + n3.y*s1.w;
    float sd = n0.x*n0.x + n0.y*n0.y + n1.x*n1.x + n1.y*n1.y +
               n2.x*n2.x + n2.y*n2.y + n3.x*n3.x + n3.y*n3.y;
    #pragma unroll
    for (int o = 16; o > 0; o >>= 1) {
        ps += __shfl_xor_sync(0xffffffffu, ps, o);
        sd += __shfl_xor_sync(0xffffffffu, sd, o);
    }
    __shared__ float bs[8], bn[8];
    __shared__ bool amLast;
    if (l == 0) {
        float np_cnt = (float)(g_cnt[lab] - 1);
        float s = 0.f, n = 0.f;
        if (np_cnt > 0.5f) {
            float possum = 10.f * (ps - sd);
            s = logf(fmaxf(g_denom[r], 1e-8f)) - possum / np_cnt;
            n = 1.f;
        }
        bs[w] = s; bn[w] = n;
    }
    __syncthreads();
    if (t == 0) {
        float S = 0.f, N = 0.f;
        #pragma unroll
        for (int k = 0; k < 8; k++) { S += bs[k]; N += bn[k]; }
        atomicAdd(&g_fsum, S);
        atomicAdd(&g_fcnt, N);
        __threadfence();
        unsigned v = atomicInc(&g_ticket, (unsigned)(BSZ / 8) - 1u);
        amLast = (v == (unsigned)(BSZ / 8) - 1u);
    }
    __syncthreads();
    if (amLast && t == 0) {
        float S = *(volatile float*)&g_fsum;
        float N = *(volatile float*)&g_fcnt;
        out[0] = S / fmaxf(N, 1.f);
    }
}

// ---------------------------------------------------------------------------
extern "C" void kernel_launch(void* const* d_in, const int* in_sizes, int n_in,
                              void* d_out, int out_size) {
    const float* lat    = (const float*)d_in[0];
    const int*   labraw = (const int*)d_in[1];
    float*       out    = (float*)d_out;

    cudaFuncSetAttribute(simdenom_kernel,
                         cudaFuncAttributeMaxDynamicSharedMemorySize,
                         SMEM_TOTAL);

    prep0_kernel<<<64, 256>>>();
    prep1_kernel<<<32, 256>>>(labraw);
    normalize_kernel<<<BSZ, DIM>>>(lat);
    simdenom_kernel<<<NCTAS, 256, SMEM_TOTAL>>>();
    finalize1_kernel<<<BSZ / 8, 256>>>(out);

    (void)in_sizes; (void)n_in; (void)out_size;
}